// round 8
// baseline (speedup 1.0000x reference)
#include <cuda_runtime.h>
#include <cstdint>

#define SQ   2048
#define ED   2048
#define NH   16
#define NG   32      // 2*H query/key heads
#define HDIM 64      // differential head dim
#define VDIM 128     // value head dim (2*HD)

static constexpr float LAMBDA_INIT = 0.78360576653162444f;

// ---- device scratch (static: no runtime allocation allowed) ----
__device__ float g_Q[SQ * ED];
__device__ float g_K[SQ * ED];
__device__ float g_V[SQ * ED];
__device__ float g_O[NG * SQ * VDIM];   // per-QK-head attention outputs
__device__ float g_X[SQ * ED];          // combined/normalized attention (S, E)
__device__ float g_lam;

// ============================================================================
// helpers
// ============================================================================
__device__ __forceinline__ unsigned f2tf(float x) {
    unsigned r;
    asm("cvt.rna.tf32.f32 %0, %1;" : "=r"(r) : "f"(x));
    return r;
}

__device__ __forceinline__ void mma_tf32(float c[4], const unsigned a[4], const unsigned b[2]) {
    asm volatile(
        "mma.sync.aligned.m16n8k8.row.col.f32.tf32.tf32.f32 "
        "{%0,%1,%2,%3}, {%4,%5,%6,%7}, {%8,%9}, {%0,%1,%2,%3};"
        : "+f"(c[0]), "+f"(c[1]), "+f"(c[2]), "+f"(c[3])
        : "r"(a[0]), "r"(a[1]), "r"(a[2]), "r"(a[3]), "r"(b[0]), "r"(b[1]));
}

__device__ __forceinline__ uint32_t smem_u32(const void* p) {
    uint32_t a;
    asm("{ .reg .u64 t; cvta.to.shared.u64 t, %1; cvt.u32.u64 %0, t; }" : "=r"(a) : "l"(p));
    return a;
}

__device__ __forceinline__ void cp16(uint32_t dst, const float* src) {
    asm volatile("cp.async.cg.shared.global [%0], [%1], 16;" :: "r"(dst), "l"(src));
}

// ============================================================================
// TF32 tensor-core GEMM (NT): C[m,n] = sum_k A[m,k] * W[n,k], 2048^3
// 128x128 CTA tile, 32-wide k tiles, 3-stage cp.async ring, ONE sync/ktile.
// 8 warps (2x4), each warp 64x32 via m16n8k8 atoms. Pitch-36 smem
// (conflict-free fragment reads, proven in R4); tf32 cvt at fragment load
// (identical values + accumulation order to R4 => identical numerics).
// ============================================================================
#define GP 36                                   // smem row pitch (fp32 words)
static constexpr int GBUF   = 128 * GP;         // words per buffer per matrix
static constexpr int GSMEMW = 3 * GBUF * 2;     // 3 bufs x (A + B)
static constexpr int GSMEMB = GSMEMW * 4;       // 110592 bytes

__global__ __launch_bounds__(256, 2) void gemm_nt(const float* __restrict__ Aext,
                                                  const float* __restrict__ W,
                                                  float* __restrict__ Cext,
                                                  int a_tag, int c_tag)
{
    extern __shared__ float gsm_f[];
    float* As = gsm_f;                 // [3][128][GP]
    float* Bs = gsm_f + 3 * GBUF;      // [3][128][GP]

    const float* A = (a_tag == 0) ? Aext : g_X;
    float* C = Cext;
    if (c_tag == 1) C = g_Q;
    else if (c_tag == 2) C = g_K;
    else if (c_tag == 3) C = g_V;

    const int t    = threadIdx.x;
    const int m0   = blockIdx.y * 128;
    const int n0   = blockIdx.x * 128;
    const int wid  = t >> 5;
    const int lane = t & 31;
    const int wm   = (wid >> 2) * 64;
    const int wn   = (wid & 3) * 32;
    const int grp  = lane >> 2;
    const int qid  = lane & 3;

    // staging coords: row = t>>1 (0..127), half = (t&1)*16 floats
    const int sr = t >> 1;
    const int sc = (t & 1) * 16;

    const uint32_t sA = smem_u32(As);
    const uint32_t sB = smem_u32(Bs);
    const float* Ap = A + (size_t)(m0 + sr) * ED + sc;
    const float* Wp = W + (size_t)(n0 + sr) * ED + sc;

    auto fill = [&](int kt) {
        const int buf = kt % 3;
        const float* ap = Ap + kt * 32;
        const float* wp = Wp + kt * 32;
        const uint32_t da = sA + (uint32_t)((buf * 128 + sr) * GP + sc) * 4u;
        const uint32_t db = sB + (uint32_t)((buf * 128 + sr) * GP + sc) * 4u;
        #pragma unroll
        for (int j = 0; j < 4; j++) {
            cp16(da + 16u * j, ap + 4 * j);
            cp16(db + 16u * j, wp + 4 * j);
        }
        asm volatile("cp.async.commit_group;" ::: "memory");
    };

    float acc[4][4][4];
    #pragma unroll
    for (int mi = 0; mi < 4; mi++)
        #pragma unroll
        for (int ni = 0; ni < 4; ni++)
            #pragma unroll
            for (int x = 0; x < 4; x++) acc[mi][ni][x] = 0.f;

    const int NKT = ED / 32;   // 64
    fill(0);
    fill(1);

    for (int kt = 0; kt < NKT; kt++) {
        if (kt < NKT - 1) asm volatile("cp.async.wait_group 1;" ::: "memory");
        else              asm volatile("cp.async.wait_group 0;" ::: "memory");
        __syncthreads();

        // prefetch 2 tiles ahead (target buffer was last read in iter kt-1,
        // and the barrier above guarantees every warp is past that read)
        if (kt + 2 < NKT) fill(kt + 2);

        const float* Ab = As + (kt % 3) * GBUF;
        const float* Bb = Bs + (kt % 3) * GBUF;

        #pragma unroll
        for (int ks = 0; ks < 4; ks++) {
            unsigned af[4][4], bf[4][2];
            #pragma unroll
            for (int mi = 0; mi < 4; mi++) {
                int r = wm + mi * 16 + grp;
                af[mi][0] = f2tf(Ab[r * GP + ks * 8 + qid]);
                af[mi][1] = f2tf(Ab[(r + 8) * GP + ks * 8 + qid]);
                af[mi][2] = f2tf(Ab[r * GP + ks * 8 + qid + 4]);
                af[mi][3] = f2tf(Ab[(r + 8) * GP + ks * 8 + qid + 4]);
            }
            #pragma unroll
            for (int ni = 0; ni < 4; ni++) {
                int r = wn + ni * 8 + grp;
                bf[ni][0] = f2tf(Bb[r * GP + ks * 8 + qid]);
                bf[ni][1] = f2tf(Bb[r * GP + ks * 8 + qid + 4]);
            }
            #pragma unroll
            for (int mi = 0; mi < 4; mi++)
                #pragma unroll
                for (int ni = 0; ni < 4; ni++)
                    mma_tf32(acc[mi][ni], af[mi], bf[ni]);
        }
    }

    #pragma unroll
    for (int mi = 0; mi < 4; mi++) {
        #pragma unroll
        for (int ni = 0; ni < 4; ni++) {
            int row = m0 + wm + mi * 16 + grp;
            int col = n0 + wn + ni * 8 + 2 * qid;
            *(float2*)&C[(size_t)row * ED + col]       = make_float2(acc[mi][ni][0], acc[mi][ni][1]);
            *(float2*)&C[(size_t)(row + 8) * ED + col] = make_float2(acc[mi][ni][2], acc[mi][ni][3]);
        }
    }
}

// ============================================================================
// lambda_full
// ============================================================================
__global__ void lam_kernel(const float* __restrict__ lq1, const float* __restrict__ lk1,
                           const float* __restrict__ lq2, const float* __restrict__ lk2)
{
    int lane = threadIdx.x;  // 64 threads
    float p1 = lq1[lane] * lk1[lane];
    float p2 = lq2[lane] * lk2[lane];
    #pragma unroll
    for (int o = 16; o > 0; o >>= 1) {
        p1 += __shfl_xor_sync(0xffffffffu, p1, o);
        p2 += __shfl_xor_sync(0xffffffffu, p2, o);
    }
    __shared__ float s1w[2], s2w[2];
    if ((lane & 31) == 0) { s1w[lane >> 5] = p1; s2w[lane >> 5] = p2; }
    __syncthreads();
    if (lane == 0)
        g_lam = expf(s1w[0] + s1w[1]) - expf(s2w[0] + s2w[1]) + LAMBDA_INIT;
}

// ============================================================================
// Tensor-core flash attention (tf32 mma, FA2-style register softmax).
// R4-proven numerics: tf32 QK and tf32 PV — differential subtraction needs
// >= tf32 mantissa on every attention operand.
// ============================================================================
__global__ __launch_bounds__(128, 2) void attn_kernel(const unsigned char* __restrict__ mask)
{
    extern __shared__ unsigned smu[];
    unsigned* Qs = smu;                    // 64 x 68 (tf32)
    unsigned* Ks = Qs + 64 * 68;           // 64 x 68 (tf32)
    unsigned* Ps = Ks + 64 * 68;           // 64 x 68 (tf32)
    unsigned* Vs = Ps + 64 * 68;           // 64 x 132 (tf32)
    float*    Ms = (float*)(Vs + 64 * 132); // 64 mask addends

    const int g    = blockIdx.y;
    const int h    = g >> 1;
    const int q0   = blockIdx.x * 64;
    const int t    = threadIdx.x;
    const int lane = t & 31;
    const int grp  = lane >> 2;
    const int qid  = lane & 3;
    const int wq   = (t >> 5) * 16;

    // stage Q tile (scaled by hd^-0.5), tf32
    for (int i = t; i < 64 * 16; i += 128) {
        int r = i >> 4, c = (i & 15) * 4;
        float4 v = *(const float4*)&g_Q[(q0 + r) * ED + g * HDIM + c];
        unsigned* dst = &Qs[r * 68 + c];
        dst[0] = f2tf(v.x * 0.125f); dst[1] = f2tf(v.y * 0.125f);
        dst[2] = f2tf(v.z * 0.125f); dst[3] = f2tf(v.w * 0.125f);
    }
    __syncthreads();

    // Q fragments held in registers for the whole kernel
    unsigned qf[8][4];
    #pragma unroll
    for (int ks = 0; ks < 8; ks++) {
        qf[ks][0] = Qs[(wq + grp) * 68 + 8 * ks + qid];
        qf[ks][1] = Qs[(wq + grp + 8) * 68 + 8 * ks + qid];
        qf[ks][2] = Qs[(wq + grp) * 68 + 8 * ks + qid + 4];
        qf[ks][3] = Qs[(wq + grp + 8) * 68 + 8 * ks + qid + 4];
    }

    float of[16][4];
    #pragma unroll
    for (int n = 0; n < 16; n++)
        #pragma unroll
        for (int x = 0; x < 4; x++) of[n][x] = 0.f;
    float m0 = -1e30f, m1 = -1e30f, l0 = 0.f, l1 = 0.f;

    for (int kt = 0; kt < SQ; kt += 64) {
        __syncthreads();
        // stage K tile (tf32)
        for (int i = t; i < 64 * 16; i += 128) {
            int r = i >> 4, c = (i & 15) * 4;
            float4 v = *(const float4*)&g_K[(kt + r) * ED + g * HDIM + c];
            unsigned* dst = &Ks[r * 68 + c];
            dst[0] = f2tf(v.x); dst[1] = f2tf(v.y); dst[2] = f2tf(v.z); dst[3] = f2tf(v.w);
        }
        // stage V tile (tf32)
        for (int i = t; i < 64 * 32; i += 128) {
            int r = i >> 5, c = (i & 31) * 4;
            float4 v = *(const float4*)&g_V[(kt + r) * ED + h * VDIM + c];
            unsigned* dst = &Vs[r * 132 + c];
            dst[0] = f2tf(v.x); dst[1] = f2tf(v.y); dst[2] = f2tf(v.z); dst[3] = f2tf(v.w);
        }
        if (t < 64) Ms[t] = mask[kt + t] ? -1e30f : 0.f;
        __syncthreads();

        // ---- scores = Q K^T (tf32 mma) ----
        float sc[8][4];
        #pragma unroll
        for (int n = 0; n < 8; n++)
            #pragma unroll
            for (int x = 0; x < 4; x++) sc[n][x] = 0.f;
        #pragma unroll
        for (int ks = 0; ks < 8; ks++) {
            unsigned kb[8][2];
            #pragma unroll
            for (int n = 0; n < 8; n++) {
                kb[n][0] = Ks[(8 * n + grp) * 68 + 8 * ks + qid];
                kb[n][1] = Ks[(8 * n + grp) * 68 + 8 * ks + qid + 4];
            }
            #pragma unroll
            for (int n = 0; n < 8; n++) mma_tf32(sc[n], qf[ks], kb[n]);
        }
        // mask addend
        #pragma unroll
        for (int n = 0; n < 8; n++) {
            float a0 = Ms[8 * n + 2 * qid], a1 = Ms[8 * n + 2 * qid + 1];
            sc[n][0] += a0; sc[n][1] += a1; sc[n][2] += a0; sc[n][3] += a1;
        }

        // ---- register online softmax (rows grp, grp+8) ----
        float mx0 = -1e30f, mx1 = -1e30f;
        #pragma unroll
        for (int n = 0; n < 8; n++) {
            mx0 = fmaxf(mx0, fmaxf(sc[n][0], sc[n][1]));
            mx1 = fmaxf(mx1, fmaxf(sc[n][2], sc[n][3]));
        }
        mx0 = fmaxf(mx0, __shfl_xor_sync(0xffffffffu, mx0, 1));
        mx0 = fmaxf(mx0, __shfl_xor_sync(0xffffffffu, mx0, 2));
        mx1 = fmaxf(mx1, __shfl_xor_sync(0xffffffffu, mx1, 1));
        mx1 = fmaxf(mx1, __shfl_xor_sync(0xffffffffu, mx1, 2));
        float mn0 = fmaxf(m0, mx0), mn1 = fmaxf(m1, mx1);
        float sum0 = 0.f, sum1 = 0.f;
        #pragma unroll
        for (int n = 0; n < 8; n++) {
            sc[n][0] = __expf(sc[n][0] - mn0); sum0 += sc[n][0];
            sc[n][1] = __expf(sc[n][1] - mn0); sum0 += sc[n][1];
            sc[n][2] = __expf(sc[n][2] - mn1); sum1 += sc[n][2];
            sc[n][3] = __expf(sc[n][3] - mn1); sum1 += sc[n][3];
        }
        sum0 += __shfl_xor_sync(0xffffffffu, sum0, 1);
        sum0 += __shfl_xor_sync(0xffffffffu, sum0, 2);
        sum1 += __shfl_xor_sync(0xffffffffu, sum1, 1);
        sum1 += __shfl_xor_sync(0xffffffffu, sum1, 2);
        float f0 = __expf(m0 - mn0), f1 = __expf(m1 - mn1);
        l0 = l0 * f0 + sum0; l1 = l1 * f1 + sum1;
        m0 = mn0; m1 = mn1;
        #pragma unroll
        for (int n = 0; n < 16; n++) {
            of[n][0] *= f0; of[n][1] *= f0; of[n][2] *= f1; of[n][3] *= f1;
        }

        // ---- P: accum layout -> A-operand layout via padded smem ----
        #pragma unroll
        for (int n = 0; n < 8; n++) {
            *(uint2*)&Ps[(wq + grp) * 68 + 8 * n + 2 * qid]     =
                make_uint2(f2tf(sc[n][0]), f2tf(sc[n][1]));
            *(uint2*)&Ps[(wq + grp + 8) * 68 + 8 * n + 2 * qid] =
                make_uint2(f2tf(sc[n][2]), f2tf(sc[n][3]));
        }
        __syncwarp();

        // ---- O += P V (tf32 mma) ----
        #pragma unroll
        for (int ks = 0; ks < 8; ks++) {
            unsigned pa[4];
            pa[0] = Ps[(wq + grp) * 68 + 8 * ks + qid];
            pa[1] = Ps[(wq + grp + 8) * 68 + 8 * ks + qid];
            pa[2] = Ps[(wq + grp) * 68 + 8 * ks + qid + 4];
            pa[3] = Ps[(wq + grp + 8) * 68 + 8 * ks + qid + 4];
            #pragma unroll
            for (int n = 0; n < 16; n++) {
                unsigned vb[2];
                vb[0] = Vs[(8 * ks + qid) * 132 + 8 * n + grp];
                vb[1] = Vs[(8 * ks + qid + 4) * 132 + 8 * n + grp];
                mma_tf32(of[n], pa, vb);
            }
        }
        __syncwarp();
    }

    float r0 = 1.f / l0, r1 = 1.f / l1;
    #pragma unroll
    for (int n = 0; n < 16; n++) {
        int row = q0 + wq + grp, col = 8 * n + 2 * qid;
        *(float2*)&g_O[(g * SQ + row) * VDIM + col]       =
            make_float2(of[n][0] * r0, of[n][1] * r0);
        *(float2*)&g_O[(g * SQ + row + 8) * VDIM + col]   =
            make_float2(of[n][2] * r1, of[n][3] * r1);
    }
}

// ============================================================================
// Epilogue: x = O[2h] - lam*O[2h+1]; RMSNorm over 128; * subln_g * (1-lam_init)
// ============================================================================
__global__ __launch_bounds__(128) void epi_kernel(const float* __restrict__ subg)
{
    const int s = blockIdx.x, h = blockIdx.y, d = threadIdx.x;
    const float lam = g_lam;
    float a = g_O[((2 * h) * SQ + s) * VDIM + d];
    float b = g_O[((2 * h + 1) * SQ + s) * VDIM + d];
    float x = a - lam * b;

    float v = x * x;
    #pragma unroll
    for (int o = 16; o > 0; o >>= 1) v += __shfl_xor_sync(0xffffffffu, v, o);
    __shared__ float ws[4];
    if ((d & 31) == 0) ws[d >> 5] = v;
    __syncthreads();
    float tot = ws[0] + ws[1] + ws[2] + ws[3];
    float rms = rsqrtf(tot * (1.f / 128.f) + 1e-5f);

    g_X[s * ED + h * VDIM + d] = x * rms * subg[d] * (1.f - LAMBDA_INIT);
}

// ============================================================================
// launch
// ============================================================================
extern "C" void kernel_launch(void* const* d_in, const int* in_sizes, int n_in,
                              void* d_out, int out_size)
{
    (void)in_sizes; (void)n_in; (void)out_size;
    const float* query = (const float*)d_in[0];
    const float* key   = (const float*)d_in[1];
    const float* value = (const float*)d_in[2];
    const unsigned char* mask = (const unsigned char*)d_in[4];
    const float* Wq  = (const float*)d_in[5];
    const float* Wk  = (const float*)d_in[6];
    const float* Wv  = (const float*)d_in[7];
    const float* Wo  = (const float*)d_in[8];
    const float* lq1 = (const float*)d_in[9];
    const float* lk1 = (const float*)d_in[10];
    const float* lq2 = (const float*)d_in[11];
    const float* lk2 = (const float*)d_in[12];
    const float* subg = (const float*)d_in[13];
    float* out = (float*)d_out;

    const int attn_smem = (3 * 64 * 68 + 64 * 132) * (int)sizeof(unsigned) + 64 * (int)sizeof(float);
    cudaFuncSetAttribute(attn_kernel, cudaFuncAttributeMaxDynamicSharedMemorySize, attn_smem);
    cudaFuncSetAttribute(gemm_nt, cudaFuncAttributeMaxDynamicSharedMemorySize, GSMEMB);

    dim3 gblk(16, 16);
    gemm_nt<<<gblk, 256, GSMEMB>>>(query, Wq, nullptr, 0, 1);
    gemm_nt<<<gblk, 256, GSMEMB>>>(key,   Wk, nullptr, 0, 2);
    gemm_nt<<<gblk, 256, GSMEMB>>>(value, Wv, nullptr, 0, 3);
    lam_kernel<<<1, 64>>>(lq1, lk1, lq2, lk2);
    attn_kernel<<<dim3(32, 32), 128, attn_smem>>>(mask);
    epi_kernel<<<dim3(SQ, NH), 128>>>(subg);
    gemm_nt<<<gblk, 256, GSMEMB>>>(nullptr, Wo, out, 1, 0);
}

// round 9
// speedup vs baseline: 1.1258x; 1.1258x over previous
#include <cuda_runtime.h>
#include <cstdint>

#define SQ   2048
#define ED   2048
#define NH   16
#define NG   32      // 2*H query/key heads
#define HDIM 64      // differential head dim
#define VDIM 128     // value head dim (2*HD)

static constexpr float LAMBDA_INIT = 0.78360576653162444f;

// ---- device scratch (static: no runtime allocation allowed) ----
__device__ float g_Q[SQ * ED];
__device__ float g_K[SQ * ED];
__device__ float g_V[SQ * ED];
__device__ float g_O[NG * SQ * VDIM];   // per-QK-head attention outputs
__device__ float g_X[SQ * ED];          // combined/normalized attention (S, E)
__device__ float g_lam;

__device__ __forceinline__ unsigned f2tf(float x) {
    unsigned r;
    asm("cvt.rna.tf32.f32 %0, %1;" : "=r"(r) : "f"(x));
    return r;
}

__device__ __forceinline__ void mma_tf32(float c[4], const unsigned a[4], const unsigned b[2]) {
    asm volatile(
        "mma.sync.aligned.m16n8k8.row.col.f32.tf32.tf32.f32 "
        "{%0,%1,%2,%3}, {%4,%5,%6,%7}, {%8,%9}, {%0,%1,%2,%3};"
        : "+f"(c[0]), "+f"(c[1]), "+f"(c[2]), "+f"(c[3])
        : "r"(a[0]), "r"(a[1]), "r"(a[2]), "r"(a[3]), "r"(b[0]), "r"(b[1]));
}

// ============================================================================
// TF32 tensor-core GEMM (NT): C[m,n] = sum_k A[m,k] * W[n,k], M=N=K=2048
// 128x128x32 block tile, 8 warps (2x4), each warp 64x32 via m16n8k8 atoms.
// R4-proven layout (pitch-36, staging-time tf32 cvt, register prefetch).
// ONLY change vs R4: __launch_bounds__(256, 2) to force <=128 regs so
// 2 CTAs co-reside per SM -> one wave (256 <= 296 slots) and barrier
// stalls covered by the co-resident CTA.
// ============================================================================
__global__ __launch_bounds__(256, 2) void gemm_nt(const float* __restrict__ Aext,
                                                  const float* __restrict__ W,
                                                  float* __restrict__ Cext,
                                                  int a_tag, int c_tag)
{
    const float* A = (a_tag == 0) ? Aext : g_X;
    float* C = Cext;
    if (c_tag == 1) C = g_Q;
    else if (c_tag == 2) C = g_K;
    else if (c_tag == 3) C = g_V;

    // pad 36: fragment reads hit bank (4*grp + qid) % 32 -> conflict-free
    __shared__ unsigned As[128][36];
    __shared__ unsigned Bs[128][36];

    const int t    = threadIdx.x;
    const int m0   = blockIdx.y * 128;
    const int n0   = blockIdx.x * 128;
    const int wid  = t >> 5;
    const int lane = t & 31;
    const int wm   = (wid >> 2) * 64;   // warp row offset in tile
    const int wn   = (wid & 3) * 32;    // warp col offset in tile
    const int grp  = lane >> 2;         // 0..7
    const int qid  = lane & 3;          // 0..3

    float acc[4][4][4];
    #pragma unroll
    for (int mi = 0; mi < 4; mi++)
        #pragma unroll
        for (int ni = 0; ni < 4; ni++)
            #pragma unroll
            for (int x = 0; x < 4; x++) acc[mi][ni][x] = 0.f;

    float4 ra[4], rb[4];

    // prefetch first k-tile
    #pragma unroll
    for (int i = 0; i < 4; i++) {
        int lin = t + 256 * i;
        int r = lin >> 3, c = (lin & 7) * 4;
        ra[i] = *(const float4*)(A + (m0 + r) * ED + c);
        rb[i] = *(const float4*)(W + (n0 + r) * ED + c);
    }

    const int NT = ED / 32;   // 64 k-tiles
    for (int kt = 0; kt < NT; kt++) {
        // stage current tile into smem (tf32-converted)
        #pragma unroll
        for (int i = 0; i < 4; i++) {
            int lin = t + 256 * i;
            int r = lin >> 3, c = (lin & 7) * 4;
            As[r][c + 0] = f2tf(ra[i].x); As[r][c + 1] = f2tf(ra[i].y);
            As[r][c + 2] = f2tf(ra[i].z); As[r][c + 3] = f2tf(ra[i].w);
            Bs[r][c + 0] = f2tf(rb[i].x); Bs[r][c + 1] = f2tf(rb[i].y);
            Bs[r][c + 2] = f2tf(rb[i].z); Bs[r][c + 3] = f2tf(rb[i].w);
        }
        __syncthreads();

        // prefetch next tile while computing
        if (kt + 1 < NT) {
            int k0 = (kt + 1) * 32;
            #pragma unroll
            for (int i = 0; i < 4; i++) {
                int lin = t + 256 * i;
                int r = lin >> 3, c = (lin & 7) * 4;
                ra[i] = *(const float4*)(A + (m0 + r) * ED + k0 + c);
                rb[i] = *(const float4*)(W + (n0 + r) * ED + k0 + c);
            }
        }

        #pragma unroll
        for (int ks = 0; ks < 4; ks++) {
            unsigned af[4][4], bf[4][2];
            #pragma unroll
            for (int mi = 0; mi < 4; mi++) {
                int r = wm + mi * 16 + grp;
                af[mi][0] = As[r][ks * 8 + qid];
                af[mi][1] = As[r + 8][ks * 8 + qid];
                af[mi][2] = As[r][ks * 8 + qid + 4];
                af[mi][3] = As[r + 8][ks * 8 + qid + 4];
            }
            #pragma unroll
            for (int ni = 0; ni < 4; ni++) {
                int r = wn + ni * 8 + grp;
                bf[ni][0] = Bs[r][ks * 8 + qid];
                bf[ni][1] = Bs[r][ks * 8 + qid + 4];
            }
            #pragma unroll
            for (int mi = 0; mi < 4; mi++)
                #pragma unroll
                for (int ni = 0; ni < 4; ni++)
                    mma_tf32(acc[mi][ni], af[mi], bf[ni]);
        }
        __syncthreads();
    }

    // epilogue: c0,c1 at (grp, 2*qid), c2,c3 at (grp+8, 2*qid)
    #pragma unroll
    for (int mi = 0; mi < 4; mi++) {
        #pragma unroll
        for (int ni = 0; ni < 4; ni++) {
            int row = m0 + wm + mi * 16 + grp;
            int col = n0 + wn + ni * 8 + 2 * qid;
            *(float2*)&C[row * ED + col]       = make_float2(acc[mi][ni][0], acc[mi][ni][1]);
            *(float2*)&C[(row + 8) * ED + col] = make_float2(acc[mi][ni][2], acc[mi][ni][3]);
        }
    }
}

// ============================================================================
// lambda_full = exp(sum(lq1*lk1)) - exp(sum(lq2*lk2)) + LAMBDA_INIT
// ============================================================================
__global__ void lam_kernel(const float* __restrict__ lq1, const float* __restrict__ lk1,
                           const float* __restrict__ lq2, const float* __restrict__ lk2)
{
    int lane = threadIdx.x;  // 64 threads
    float p1 = lq1[lane] * lk1[lane];
    float p2 = lq2[lane] * lk2[lane];
    #pragma unroll
    for (int o = 16; o > 0; o >>= 1) {
        p1 += __shfl_xor_sync(0xffffffffu, p1, o);
        p2 += __shfl_xor_sync(0xffffffffu, p2, o);
    }
    __shared__ float s1w[2], s2w[2];
    if ((lane & 31) == 0) { s1w[lane >> 5] = p1; s2w[lane >> 5] = p2; }
    __syncthreads();
    if (lane == 0)
        g_lam = expf(s1w[0] + s1w[1]) - expf(s2w[0] + s2w[1]) + LAMBDA_INIT;
}

// ============================================================================
// Tensor-core flash attention (tf32 mma, FA2-style register softmax).
// Block: 128 threads (4 warps), 64 query rows of one QK-head g.
// Warp w owns query rows [w*16, w*16+16). Scores/O stay in mma accumulators.
// R4-proven numerics: tf32 QK and tf32 PV — differential subtraction needs
// >= tf32 mantissa on every attention operand.
// ============================================================================
__global__ __launch_bounds__(128, 2) void attn_kernel(const unsigned char* __restrict__ mask)
{
    extern __shared__ unsigned smu[];
    unsigned* Qs = smu;                    // 64 x 68 (tf32)
    unsigned* Ks = Qs + 64 * 68;           // 64 x 68 (tf32)
    unsigned* Ps = Ks + 64 * 68;           // 64 x 68 (tf32)
    unsigned* Vs = Ps + 64 * 68;           // 64 x 132 (tf32)
    float*    Ms = (float*)(Vs + 64 * 132); // 64 mask addends

    const int g    = blockIdx.y;
    const int h    = g >> 1;
    const int q0   = blockIdx.x * 64;
    const int t    = threadIdx.x;
    const int lane = t & 31;
    const int grp  = lane >> 2;
    const int qid  = lane & 3;
    const int wq   = (t >> 5) * 16;

    // stage Q tile (scaled by hd^-0.5), tf32
    for (int i = t; i < 64 * 16; i += 128) {
        int r = i >> 4, c = (i & 15) * 4;
        float4 v = *(const float4*)&g_Q[(q0 + r) * ED + g * HDIM + c];
        unsigned* dst = &Qs[r * 68 + c];
        dst[0] = f2tf(v.x * 0.125f); dst[1] = f2tf(v.y * 0.125f);
        dst[2] = f2tf(v.z * 0.125f); dst[3] = f2tf(v.w * 0.125f);
    }
    __syncthreads();

    // Q fragments held in registers for the whole kernel
    unsigned qf[8][4];
    #pragma unroll
    for (int ks = 0; ks < 8; ks++) {
        qf[ks][0] = Qs[(wq + grp) * 68 + 8 * ks + qid];
        qf[ks][1] = Qs[(wq + grp + 8) * 68 + 8 * ks + qid];
        qf[ks][2] = Qs[(wq + grp) * 68 + 8 * ks + qid + 4];
        qf[ks][3] = Qs[(wq + grp + 8) * 68 + 8 * ks + qid + 4];
    }

    float of[16][4];
    #pragma unroll
    for (int n = 0; n < 16; n++)
        #pragma unroll
        for (int x = 0; x < 4; x++) of[n][x] = 0.f;
    float m0 = -1e30f, m1 = -1e30f, l0 = 0.f, l1 = 0.f;

    for (int kt = 0; kt < SQ; kt += 64) {
        __syncthreads();
        // stage K tile (tf32)
        for (int i = t; i < 64 * 16; i += 128) {
            int r = i >> 4, c = (i & 15) * 4;
            float4 v = *(const float4*)&g_K[(kt + r) * ED + g * HDIM + c];
            unsigned* dst = &Ks[r * 68 + c];
            dst[0] = f2tf(v.x); dst[1] = f2tf(v.y); dst[2] = f2tf(v.z); dst[3] = f2tf(v.w);
        }
        // stage V tile (tf32)
        for (int i = t; i < 64 * 32; i += 128) {
            int r = i >> 5, c = (i & 31) * 4;
            float4 v = *(const float4*)&g_V[(kt + r) * ED + h * VDIM + c];
            unsigned* dst = &Vs[r * 132 + c];
            dst[0] = f2tf(v.x); dst[1] = f2tf(v.y); dst[2] = f2tf(v.z); dst[3] = f2tf(v.w);
        }
        if (t < 64) Ms[t] = mask[kt + t] ? -1e30f : 0.f;
        __syncthreads();

        // ---- scores = Q K^T (tf32 mma) ----
        float sc[8][4];
        #pragma unroll
        for (int n = 0; n < 8; n++)
            #pragma unroll
            for (int x = 0; x < 4; x++) sc[n][x] = 0.f;
        #pragma unroll
        for (int ks = 0; ks < 8; ks++) {
            unsigned kb[8][2];
            #pragma unroll
            for (int n = 0; n < 8; n++) {
                kb[n][0] = Ks[(8 * n + grp) * 68 + 8 * ks + qid];
                kb[n][1] = Ks[(8 * n + grp) * 68 + 8 * ks + qid + 4];
            }
            #pragma unroll
            for (int n = 0; n < 8; n++) mma_tf32(sc[n], qf[ks], kb[n]);
        }
        // mask addend
        #pragma unroll
        for (int n = 0; n < 8; n++) {
            float a0 = Ms[8 * n + 2 * qid], a1 = Ms[8 * n + 2 * qid + 1];
            sc[n][0] += a0; sc[n][1] += a1; sc[n][2] += a0; sc[n][3] += a1;
        }

        // ---- register online softmax (rows grp, grp+8) ----
        float mx0 = -1e30f, mx1 = -1e30f;
        #pragma unroll
        for (int n = 0; n < 8; n++) {
            mx0 = fmaxf(mx0, fmaxf(sc[n][0], sc[n][1]));
            mx1 = fmaxf(mx1, fmaxf(sc[n][2], sc[n][3]));
        }
        mx0 = fmaxf(mx0, __shfl_xor_sync(0xffffffffu, mx0, 1));
        mx0 = fmaxf(mx0, __shfl_xor_sync(0xffffffffu, mx0, 2));
        mx1 = fmaxf(mx1, __shfl_xor_sync(0xffffffffu, mx1, 1));
        mx1 = fmaxf(mx1, __shfl_xor_sync(0xffffffffu, mx1, 2));
        float mn0 = fmaxf(m0, mx0), mn1 = fmaxf(m1, mx1);
        float sum0 = 0.f, sum1 = 0.f;
        #pragma unroll
        for (int n = 0; n < 8; n++) {
            sc[n][0] = __expf(sc[n][0] - mn0); sum0 += sc[n][0];
            sc[n][1] = __expf(sc[n][1] - mn0); sum0 += sc[n][1];
            sc[n][2] = __expf(sc[n][2] - mn1); sum1 += sc[n][2];
            sc[n][3] = __expf(sc[n][3] - mn1); sum1 += sc[n][3];
        }
        sum0 += __shfl_xor_sync(0xffffffffu, sum0, 1);
        sum0 += __shfl_xor_sync(0xffffffffu, sum0, 2);
        sum1 += __shfl_xor_sync(0xffffffffu, sum1, 1);
        sum1 += __shfl_xor_sync(0xffffffffu, sum1, 2);
        float f0 = __expf(m0 - mn0), f1 = __expf(m1 - mn1);
        l0 = l0 * f0 + sum0; l1 = l1 * f1 + sum1;
        m0 = mn0; m1 = mn1;
        #pragma unroll
        for (int n = 0; n < 16; n++) {
            of[n][0] *= f0; of[n][1] *= f0; of[n][2] *= f1; of[n][3] *= f1;
        }

        // ---- P: accum layout -> A-operand layout via padded smem ----
        #pragma unroll
        for (int n = 0; n < 8; n++) {
            *(uint2*)&Ps[(wq + grp) * 68 + 8 * n + 2 * qid]     =
                make_uint2(f2tf(sc[n][0]), f2tf(sc[n][1]));
            *(uint2*)&Ps[(wq + grp + 8) * 68 + 8 * n + 2 * qid] =
                make_uint2(f2tf(sc[n][2]), f2tf(sc[n][3]));
        }
        __syncwarp();

        // ---- O += P V (tf32 mma) ----
        #pragma unroll
        for (int ks = 0; ks < 8; ks++) {
            unsigned pa[4];
            pa[0] = Ps[(wq + grp) * 68 + 8 * ks + qid];
            pa[1] = Ps[(wq + grp + 8) * 68 + 8 * ks + qid];
            pa[2] = Ps[(wq + grp) * 68 + 8 * ks + qid + 4];
            pa[3] = Ps[(wq + grp + 8) * 68 + 8 * ks + qid + 4];
            #pragma unroll
            for (int n = 0; n < 16; n++) {
                unsigned vb[2];
                vb[0] = Vs[(8 * ks + qid) * 132 + 8 * n + grp];
                vb[1] = Vs[(8 * ks + qid + 4) * 132 + 8 * n + grp];
                mma_tf32(of[n], pa, vb);
            }
        }
        __syncwarp();
    }

    float r0 = 1.f / l0, r1 = 1.f / l1;
    #pragma unroll
    for (int n = 0; n < 16; n++) {
        int row = q0 + wq + grp, col = 8 * n + 2 * qid;
        *(float2*)&g_O[(g * SQ + row) * VDIM + col]       =
            make_float2(of[n][0] * r0, of[n][1] * r0);
        *(float2*)&g_O[(g * SQ + row + 8) * VDIM + col]   =
            make_float2(of[n][2] * r1, of[n][3] * r1);
    }
}

// ============================================================================
// Epilogue: x = O[2h] - lam*O[2h+1]; RMSNorm over 128; * subln_g * (1-lam_init)
// ============================================================================
__global__ __launch_bounds__(128) void epi_kernel(const float* __restrict__ subg)
{
    const int s = blockIdx.x, h = blockIdx.y, d = threadIdx.x;
    const float lam = g_lam;
    float a = g_O[((2 * h) * SQ + s) * VDIM + d];
    float b = g_O[((2 * h + 1) * SQ + s) * VDIM + d];
    float x = a - lam * b;

    float v = x * x;
    #pragma unroll
    for (int o = 16; o > 0; o >>= 1) v += __shfl_xor_sync(0xffffffffu, v, o);
    __shared__ float ws[4];
    if ((d & 31) == 0) ws[d >> 5] = v;
    __syncthreads();
    float tot = ws[0] + ws[1] + ws[2] + ws[3];
    float rms = rsqrtf(tot * (1.f / 128.f) + 1e-5f);

    g_X[s * ED + h * VDIM + d] = x * rms * subg[d] * (1.f - LAMBDA_INIT);
}

// ============================================================================
// launch
// ============================================================================
extern "C" void kernel_launch(void* const* d_in, const int* in_sizes, int n_in,
                              void* d_out, int out_size)
{
    (void)in_sizes; (void)n_in; (void)out_size;
    const float* query = (const float*)d_in[0];
    const float* key   = (const float*)d_in[1];
    const float* value = (const float*)d_in[2];
    const unsigned char* mask = (const unsigned char*)d_in[4];
    const float* Wq  = (const float*)d_in[5];
    const float* Wk  = (const float*)d_in[6];
    const float* Wv  = (const float*)d_in[7];
    const float* Wo  = (const float*)d_in[8];
    const float* lq1 = (const float*)d_in[9];
    const float* lk1 = (const float*)d_in[10];
    const float* lq2 = (const float*)d_in[11];
    const float* lk2 = (const float*)d_in[12];
    const float* subg = (const float*)d_in[13];
    float* out = (float*)d_out;

    const int attn_smem = (3 * 64 * 68 + 64 * 132) * (int)sizeof(unsigned) + 64 * (int)sizeof(float);
    cudaFuncSetAttribute(attn_kernel, cudaFuncAttributeMaxDynamicSharedMemorySize, attn_smem);

    dim3 gblk(16, 16);
    gemm_nt<<<gblk, 256>>>(query, Wq, nullptr, 0, 1);
    gemm_nt<<<gblk, 256>>>(key,   Wk, nullptr, 0, 2);
    gemm_nt<<<gblk, 256>>>(value, Wv, nullptr, 0, 3);
    lam_kernel<<<1, 64>>>(lq1, lk1, lq2, lk2);
    attn_kernel<<<dim3(32, 32), 128, attn_smem>>>(mask);
    epi_kernel<<<dim3(SQ, NH), 128>>>(subg);
    gemm_nt<<<gblk, 256>>>(nullptr, Wo, out, 1, 0);
}